// round 2
// baseline (speedup 1.0000x reference)
#include <cuda_runtime.h>
#include <math.h>

#define NP 64
#define MM 512
#define DD 256
#define MARGIN 0.2f

// Scratch (allocation-free rule: __device__ globals)
__device__ float g_dist[(size_t)NP * MM * MM];   // 64 MiB distance matrix
__device__ float g_norm[NP * MM];
__device__ int   g_label[NP * MM];
__device__ float g_psum[NP];
__device__ float g_pcnt[NP];

// ---------------------------------------------------------------------------
// prep: normalize labels to int32 (handles int32 or int64-little-endian input)
// and zero the per-part accumulators.
// ---------------------------------------------------------------------------
__global__ void prep_kernel(const int* __restrict__ raw) {
    int is32 = (raw[33] != 0);
    int p = blockIdx.x;
    for (int c = threadIdx.x; c < MM; c += blockDim.x) {
        int idx = p * MM + c;
        g_label[idx] = is32 ? raw[idx] : raw[idx << 1];
    }
    if (p == 0 && threadIdx.x < NP) {
        g_psum[threadIdx.x] = 0.f;
        g_pcnt[threadIdx.x] = 0.f;
    }
}

// ---------------------------------------------------------------------------
// norms: one warp per row, ||x||^2 over 256 floats
// ---------------------------------------------------------------------------
__global__ __launch_bounds__(256) void norm_kernel(const float* __restrict__ feat) {
    int row  = (blockIdx.x << 3) + (threadIdx.x >> 5);
    int lane = threadIdx.x & 31;
    const float4* f = reinterpret_cast<const float4*>(feat + (size_t)row * DD);
    float s = 0.f;
#pragma unroll
    for (int u = 0; u < 2; u++) {
        float4 v = f[lane + (u << 5)];
        s += v.x * v.x + v.y * v.y + v.z * v.z + v.w * v.w;
    }
#pragma unroll
    for (int o = 16; o; o >>= 1) s += __shfl_xor_sync(0xffffffffu, s, o);
    if (lane == 0) g_norm[row] = s;
}

// ---------------------------------------------------------------------------
// batched gram GEMM -> Euclidean distance matrix
// ---------------------------------------------------------------------------
#define TILE 64
#define BK 32
__global__ __launch_bounds__(256) void gemm_kernel(const float* __restrict__ feat) {
    __shared__ float As[BK][TILE];
    __shared__ float Bs[BK][TILE];
    int p  = blockIdx.z;
    int by = blockIdx.y, bx = blockIdx.x;
    const float* base = feat + (size_t)p * MM * DD;
    int tid = threadIdx.x;
    int tx = tid & 15, ty = tid >> 4;
    float acc[4][4] = {};
    const float* Arow = base + (size_t)(by * TILE) * DD;
    const float* Brow = base + (size_t)(bx * TILE) * DD;

    for (int k0 = 0; k0 < DD; k0 += BK) {
        __syncthreads();
#pragma unroll
        for (int t = 0; t < 2; t++) {
            int q  = tid + (t << 8);
            int i  = q >> 3;
            int kk = (q & 7) << 2;
            float4 a = *(const float4*)(Arow + (size_t)i * DD + k0 + kk);
            As[kk + 0][i] = a.x; As[kk + 1][i] = a.y;
            As[kk + 2][i] = a.z; As[kk + 3][i] = a.w;
            float4 b = *(const float4*)(Brow + (size_t)i * DD + k0 + kk);
            Bs[kk + 0][i] = b.x; Bs[kk + 1][i] = b.y;
            Bs[kk + 2][i] = b.z; Bs[kk + 3][i] = b.w;
        }
        __syncthreads();
#pragma unroll
        for (int k = 0; k < BK; k++) {
            float a[4], b[4];
            *(float4*)a = *(const float4*)&As[k][ty << 2];
            *(float4*)b = *(const float4*)&Bs[k][tx << 2];
#pragma unroll
            for (int u = 0; u < 4; u++)
#pragma unroll
                for (int v = 0; v < 4; v++)
                    acc[u][v] = fmaf(a[u], b[v], acc[u][v]);
        }
    }

    int i0 = by * TILE + (ty << 2);
    int j0 = bx * TILE + (tx << 2);
    float ni[4], nj[4];
#pragma unroll
    for (int u = 0; u < 4; u++) {
        ni[u] = g_norm[p * MM + i0 + u];
        nj[u] = g_norm[p * MM + j0 + u];
    }
#pragma unroll
    for (int u = 0; u < 4; u++) {
        float4 o;
        o.x = sqrtf(fmaxf(ni[u] + nj[0] - 2.f * acc[u][0], 0.f));
        o.y = sqrtf(fmaxf(ni[u] + nj[1] - 2.f * acc[u][1], 0.f));
        o.z = sqrtf(fmaxf(ni[u] + nj[2] - 2.f * acc[u][2], 0.f));
        o.w = sqrtf(fmaxf(ni[u] + nj[3] - 2.f * acc[u][3], 0.f));
        *(float4*)&g_dist[((size_t)(p * MM + i0 + u)) * MM + j0] = o;
    }
}

// ---------------------------------------------------------------------------
// hinge: one warp per anchor; suffix-sum trick collapses the 16x inner loop.
//  idx = #{C <= d_q}  in [0,16]  (4-step search covers [0,15]; 17th outcome
//  handled by the hi = (Sw[15] <= d_q) select; sT[16] = (0,0) => zero contrib)
// ---------------------------------------------------------------------------
__global__ __launch_bounds__(256) void hinge_kernel() {
    __shared__ int    slbl[MM];
    __shared__ float  sraw[8][16];
    __shared__ float  ssort[8][16];
    __shared__ float2 sT[8][17];

    int tid  = threadIdx.x;
    int w    = tid >> 5, lane = tid & 31;
    int blk  = blockIdx.x;
    int p    = blk >> 6;
    int i    = ((blk & 63) << 3) + w;

    for (int c = tid; c < MM; c += 256) slbl[c] = g_label[p * MM + c];
    __syncthreads();

    const float* row = g_dist + ((size_t)(p * MM + i)) * MM;
    int La = slbl[i];

    // 1. gather positives
    int npos = 0;
#pragma unroll 1
    for (int it = 0; it < 16; it++) {
        int c = (it << 5) + lane;
        bool m = (slbl[c] == La);
        unsigned bm = __ballot_sync(0xffffffffu, m);
        if (m) {
            int off = npos + __popc(bm & ((1u << lane) - 1u));
            if (off < 16) sraw[w][off] = MARGIN + row[c];
        }
        npos += __popc(bm);
    }
    if (npos > 16) npos = 16;
    __syncwarp();

    // 2. rank sort into ssort, pad with +inf
    if (lane < 16) {
        if (lane < npos) {
            float v = sraw[w][lane];
            int r = 0;
            for (int j = 0; j < npos; j++) {
                float u = sraw[w][j];
                r += (int)((u < v) | ((u == v) & (j < lane)));
            }
            ssort[w][r] = v;
        } else {
            ssort[w][lane] = 3.4e38f;
        }
    }
    __syncwarp();

    // 3. suffix sums + remaining-count table (sT[16] = (0,0))
    if (lane <= 16) {
        float ss = 0.f;
        for (int t = lane; t < npos; t++) ss += ssort[w][t];
        sT[w][lane] = make_float2(ss, (float)(npos - lane));
    }
    __syncwarp();

    // 4. main loop over all 512 columns
    float accA = 0.f, accB = 0.f, accC = 0.f;
    const float* Sw = ssort[w];
#pragma unroll
    for (int it = 0; it < 16; it++) {
        int c = (it << 5) + lane;
        float dq = row[c];
        int hi  = (Sw[15] <= dq);                 // count == 16 case
        int idx = (Sw[7] <= dq) ? 8 : 0;
        idx += (Sw[idx + 3] <= dq) ? 4 : 0;
        idx += (Sw[idx + 1] <= dq) ? 2 : 0;
        idx += (Sw[idx]     <= dq) ? 1 : 0;
        idx = hi ? 16 : idx;
        if (slbl[c] != La) {
            float2 t = sT[w][idx];
            accA += t.x;
            accB  = fmaf(t.y, dq, accB);
            accC += t.y;
        }
    }

    float loss = accA - accB;
#pragma unroll
    for (int o = 16; o; o >>= 1) {
        loss += __shfl_xor_sync(0xffffffffu, loss, o);
        accC += __shfl_xor_sync(0xffffffffu, accC, o);
    }
    if (lane == 0) {
        atomicAdd(&g_psum[p], loss);
        atomicAdd(&g_pcnt[p], accC);
    }
}

// ---------------------------------------------------------------------------
// epilogue
// ---------------------------------------------------------------------------
__global__ void final_kernel(float* __restrict__ out, int out_size) {
    if (threadIdx.x == 0 && blockIdx.x == 0) {
        float a = 0.f, b = 0.f;
        for (int p = 0; p < NP; p++) {
            float c = g_pcnt[p];
            a += (c > 0.f) ? (g_psum[p] / fmaxf(c, 1.f)) : 0.f;
            b += c;
        }
        out[0] = a / (float)NP;
        if (out_size > 1) out[1] = b / (float)NP;
    }
}

extern "C" void kernel_launch(void* const* d_in, const int* in_sizes, int n_in,
                              void* d_out, int out_size) {
    const float* feat   = (const float*)d_in[0];
    const int*   rawlbl = (const int*)d_in[1];
    (void)in_sizes; (void)n_in;

    prep_kernel<<<NP, 256>>>(rawlbl);
    norm_kernel<<<4096, 256>>>(feat);
    dim3 g(8, 8, NP);
    gemm_kernel<<<g, 256>>>(feat);
    hinge_kernel<<<4096, 256>>>();
    final_kernel<<<1, 32>>>((float*)d_out, out_size);
}

// round 4
// speedup vs baseline: 2.3403x; 2.3403x over previous
#include <cuda_runtime.h>
#include <cuda_bf16.h>
#include <cstdint>
#include <math.h>

#define NP 64
#define MM 512
#define DD 256
#define MARGIN 0.2f

__device__ float g_dist[(size_t)NP * MM * MM];   // 64 MiB distance matrix
__device__ float g_norm[NP * MM];
__device__ int   g_label[NP * MM];
__device__ float g_psum[NP];
__device__ float g_pcnt[NP];

// upper-triangle tile map (4x4 -> 10 tiles)
__constant__ int c_by[10] = {0,0,0,0,1,1,1,2,2,3};
__constant__ int c_bx[10] = {0,1,2,3,1,2,3,2,3,3};

// ---------------------------------------------------------------------------
__global__ void prep_kernel(const int* __restrict__ raw) {
    int is32 = (raw[33] != 0);
    int p = blockIdx.x;
    for (int c = threadIdx.x; c < MM; c += blockDim.x) {
        int idx = p * MM + c;
        g_label[idx] = is32 ? raw[idx] : raw[idx << 1];
    }
    if (p == 0 && threadIdx.x < NP) {
        g_psum[threadIdx.x] = 0.f;
        g_pcnt[threadIdx.x] = 0.f;
    }
}

__global__ __launch_bounds__(256) void norm_kernel(const float* __restrict__ feat) {
    int row  = (blockIdx.x << 3) + (threadIdx.x >> 5);
    int lane = threadIdx.x & 31;
    const float4* f = reinterpret_cast<const float4*>(feat + (size_t)row * DD);
    float s = 0.f;
#pragma unroll
    for (int u = 0; u < 2; u++) {
        float4 v = f[lane + (u << 5)];
        s += v.x * v.x + v.y * v.y + v.z * v.z + v.w * v.w;
    }
#pragma unroll
    for (int o = 16; o; o >>= 1) s += __shfl_xor_sync(0xffffffffu, s, o);
    if (lane == 0) g_norm[row] = s;
}

// ---------------------------------------------------------------------------
// bf16 split: x = hi + lo, both rn-rounded bf16 (error ~2^-17 relative)
// ---------------------------------------------------------------------------
__device__ __forceinline__ void split2(float x0, float x1, uint32_t& hi, uint32_t& lo) {
    uint32_t h;
    asm("cvt.rn.bf16x2.f32 %0, %1, %2;" : "=r"(h) : "f"(x1), "f"(x0));
    float h0 = __uint_as_float(h << 16);
    float h1 = __uint_as_float(h & 0xFFFF0000u);
    float r0 = x0 - h0, r1 = x1 - h1;
    asm("cvt.rn.bf16x2.f32 %0, %1, %2;" : "=r"(lo) : "f"(r1), "f"(r0));
    hi = h;
}

#define MMA16816(c0,c1,c2,c3, a0,a1,a2,a3, b0,b1) \
    asm volatile("mma.sync.aligned.m16n8k16.row.col.f32.bf16.bf16.f32 " \
                 "{%0,%1,%2,%3}, {%4,%5,%6,%7}, {%8,%9}, {%0,%1,%2,%3};" \
                 : "+f"(c0), "+f"(c1), "+f"(c2), "+f"(c3) \
                 : "r"(a0), "r"(a1), "r"(a2), "r"(a3), "r"(b0), "r"(b1))

// SMEM layout (dynamic)
#define LDA 40                        // bf16 row stride (32 + 8 pad): conflict-free frags
#define TILE_B (128 * LDA * 2)        // 10240 bytes per bf16 tile
#define OFF_AHI 0
#define OFF_ALO (TILE_B)
#define OFF_BHI (2 * TILE_B)
#define OFF_BLO (3 * TILE_B)
#define OFF_NRM (4 * TILE_B)          // 40960: sNi[128], sNj[128]
#define OFF_CT  (OFF_NRM + 1024)      // 41984: 128 x 129 f32 transpose tile
#define SMEM_TOTAL (OFF_CT + 128 * 129 * 4)   // 108032 B

// Load + split one 128x32 f32 chunk into hi/lo bf16 smem tiles
__device__ __forceinline__ void load_chunk(
    const float* __restrict__ src, int k0, char* smem, int off_hi, int off_lo, int tid)
{
    uint16_t* shi = reinterpret_cast<uint16_t*>(smem + off_hi);
    uint16_t* slo = reinterpret_cast<uint16_t*>(smem + off_lo);
#pragma unroll
    for (int it = 0; it < 4; it++) {
        int q   = tid + (it << 8);     // 0..1023 float4 slots
        int row = q >> 3;
        int c4  = q & 7;
        float4 v = *reinterpret_cast<const float4*>(src + (size_t)row * DD + k0 + (c4 << 2));
        uint32_t h0, h1, l0, l1;
        split2(v.x, v.y, h0, l0);
        split2(v.z, v.w, h1, l1);
        int idx = row * LDA + (c4 << 2);
        *reinterpret_cast<uint2*>(&shi[idx]) = make_uint2(h0, h1);
        *reinterpret_cast<uint2*>(&slo[idx]) = make_uint2(l0, l1);
    }
}

// ---------------------------------------------------------------------------
// HMMA GEMM: dist tile [128,128] for (by,bx) of part p; bf16-split 3 products
// ---------------------------------------------------------------------------
__global__ void __launch_bounds__(256, 1) mma_gemm_kernel(const float* __restrict__ feat) {
    extern __shared__ char smem[];
    const int tid = threadIdx.x;
    const int w = tid >> 5, lane = tid & 31;
    const int g = lane >> 2, tg = lane & 3;
    const int wm = w >> 1, wn = w & 1;
    const int t = blockIdx.x, p = blockIdx.y;
    const int by = c_by[t], bx = c_bx[t];
    const bool diag = (bx == by);

    float* sNi = reinterpret_cast<float*>(smem + OFF_NRM);
    float* sNj = sNi + 128;
    if (tid < 128) {
        sNi[tid] = g_norm[p * MM + by * 128 + tid];
        sNj[tid] = g_norm[p * MM + bx * 128 + tid];
    }

    const float* Abase = feat + ((size_t)p * MM + (size_t)by * 128) * DD;
    const float* Bbase = feat + ((size_t)p * MM + (size_t)bx * 128) * DD;

    const uint16_t* sAhi = reinterpret_cast<const uint16_t*>(smem + OFF_AHI);
    const uint16_t* sAlo = reinterpret_cast<const uint16_t*>(smem + OFF_ALO);
    const uint16_t* sBhi = reinterpret_cast<const uint16_t*>(smem + (diag ? OFF_AHI : OFF_BHI));
    const uint16_t* sBlo = reinterpret_cast<const uint16_t*>(smem + (diag ? OFF_ALO : OFF_BLO));

    float c[2][8][4];
#pragma unroll
    for (int mi = 0; mi < 2; mi++)
#pragma unroll
        for (int ni = 0; ni < 8; ni++)
#pragma unroll
            for (int r = 0; r < 4; r++) c[mi][ni][r] = 0.f;

#pragma unroll 1
    for (int ch = 0; ch < 8; ch++) {
        int k0 = ch << 5;
        __syncthreads();
        load_chunk(Abase, k0, smem, OFF_AHI, OFF_ALO, tid);
        if (!diag) load_chunk(Bbase, k0, smem, OFF_BHI, OFF_BLO, tid);
        __syncthreads();

#pragma unroll
        for (int ks = 0; ks < 2; ks++) {
            int kk = (ks << 4) + (tg << 1);
            uint32_t ah[2][4], al[2][4];
#pragma unroll
            for (int mi = 0; mi < 2; mi++) {
                int r0 = ((wm << 5) + (mi << 4) + g) * LDA + kk;
                int r1 = r0 + (LDA << 3);
                ah[mi][0] = *reinterpret_cast<const uint32_t*>(&sAhi[r0]);
                ah[mi][1] = *reinterpret_cast<const uint32_t*>(&sAhi[r1]);
                ah[mi][2] = *reinterpret_cast<const uint32_t*>(&sAhi[r0 + 8]);
                ah[mi][3] = *reinterpret_cast<const uint32_t*>(&sAhi[r1 + 8]);
                al[mi][0] = *reinterpret_cast<const uint32_t*>(&sAlo[r0]);
                al[mi][1] = *reinterpret_cast<const uint32_t*>(&sAlo[r1]);
                al[mi][2] = *reinterpret_cast<const uint32_t*>(&sAlo[r0 + 8]);
                al[mi][3] = *reinterpret_cast<const uint32_t*>(&sAlo[r1 + 8]);
            }
            uint32_t bh[8][2], bl[8][2];
#pragma unroll
            for (int ni = 0; ni < 8; ni++) {
                int rb = ((wn << 6) + (ni << 3) + g) * LDA + kk;
                bh[ni][0] = *reinterpret_cast<const uint32_t*>(&sBhi[rb]);
                bh[ni][1] = *reinterpret_cast<const uint32_t*>(&sBhi[rb + 8]);
                bl[ni][0] = *reinterpret_cast<const uint32_t*>(&sBlo[rb]);
                bl[ni][1] = *reinterpret_cast<const uint32_t*>(&sBlo[rb + 8]);
            }
#pragma unroll
            for (int mi = 0; mi < 2; mi++)
#pragma unroll
                for (int ni = 0; ni < 8; ni++) {
                    MMA16816(c[mi][ni][0], c[mi][ni][1], c[mi][ni][2], c[mi][ni][3],
                             ah[mi][0], ah[mi][1], ah[mi][2], ah[mi][3],
                             bh[ni][0], bh[ni][1]);
                    MMA16816(c[mi][ni][0], c[mi][ni][1], c[mi][ni][2], c[mi][ni][3],
                             ah[mi][0], ah[mi][1], ah[mi][2], ah[mi][3],
                             bl[ni][0], bl[ni][1]);
                    MMA16816(c[mi][ni][0], c[mi][ni][1], c[mi][ni][2], c[mi][ni][3],
                             al[mi][0], al[mi][1], al[mi][2], al[mi][3],
                             bh[ni][0], bh[ni][1]);
                }
        }
    }

    // epilogue: dv = sqrt(relu(ni + nj - 2 dot)); direct stores + smem transpose
    __syncthreads();   // operand smem dead; sCt region is separate anyway
    float* sCt = reinterpret_cast<float*>(smem + OFF_CT);
#pragma unroll
    for (int mi = 0; mi < 2; mi++) {
        int i0 = (wm << 5) + (mi << 4) + g;
#pragma unroll
        for (int ni = 0; ni < 8; ni++) {
            int j0 = (wn << 6) + (ni << 3) + (tg << 1);
            float d0 = sqrtf(fmaxf(sNi[i0]     + sNj[j0]     - 2.f * c[mi][ni][0], 0.f));
            float d1 = sqrtf(fmaxf(sNi[i0]     + sNj[j0 + 1] - 2.f * c[mi][ni][1], 0.f));
            float d2 = sqrtf(fmaxf(sNi[i0 + 8] + sNj[j0]     - 2.f * c[mi][ni][2], 0.f));
            float d3 = sqrtf(fmaxf(sNi[i0 + 8] + sNj[j0 + 1] - 2.f * c[mi][ni][3], 0.f));
            float* dr0 = g_dist + ((size_t)(p * MM + by * 128 + i0)) * MM + bx * 128 + j0;
            *reinterpret_cast<float2*>(dr0)            = make_float2(d0, d1);
            *reinterpret_cast<float2*>(dr0 + 8 * MM)   = make_float2(d2, d3);
            if (!diag) {
                sCt[i0 * 129 + j0]           = d0;
                sCt[i0 * 129 + j0 + 1]       = d1;
                sCt[(i0 + 8) * 129 + j0]     = d2;
                sCt[(i0 + 8) * 129 + j0 + 1] = d3;
            }
        }
    }
    if (!diag) {
        __syncthreads();
#pragma unroll 1
        for (int jj = w << 4; jj < (w << 4) + 16; jj++) {
            float* orow = g_dist + ((size_t)(p * MM + bx * 128 + jj)) * MM + by * 128;
#pragma unroll
            for (int tt = 0; tt < 4; tt++)
                orow[lane + (tt << 5)] = sCt[(lane + (tt << 5)) * 129 + jj];
        }
    }
}

// ---------------------------------------------------------------------------
// hinge (unchanged passing version)
// ---------------------------------------------------------------------------
__global__ __launch_bounds__(256) void hinge_kernel() {
    __shared__ int    slbl[MM];
    __shared__ float  sraw[8][16];
    __shared__ float  ssort[8][16];
    __shared__ float2 sT[8][17];

    int tid  = threadIdx.x;
    int w    = tid >> 5, lane = tid & 31;
    int blk  = blockIdx.x;
    int p    = blk >> 6;
    int i    = ((blk & 63) << 3) + w;

    for (int c = tid; c < MM; c += 256) slbl[c] = g_label[p * MM + c];
    __syncthreads();

    const float* row = g_dist + ((size_t)(p * MM + i)) * MM;
    int La = slbl[i];

    int npos = 0;
#pragma unroll 1
    for (int it = 0; it < 16; it++) {
        int c = (it << 5) + lane;
        bool m = (slbl[c] == La);
        unsigned bm = __ballot_sync(0xffffffffu, m);
        if (m) {
            int off = npos + __popc(bm & ((1u << lane) - 1u));
            if (off < 16) sraw[w][off] = MARGIN + row[c];
        }
        npos += __popc(bm);
    }
    if (npos > 16) npos = 16;
    __syncwarp();

    if (lane < 16) {
        if (lane < npos) {
            float v = sraw[w][lane];
            int r = 0;
            for (int j = 0; j < npos; j++) {
                float u = sraw[w][j];
                r += (int)((u < v) | ((u == v) & (j < lane)));
            }
            ssort[w][r] = v;
        } else {
            ssort[w][lane] = 3.4e38f;
        }
    }
    __syncwarp();

    if (lane <= 16) {
        float ss = 0.f;
        for (int t = lane; t < npos; t++) ss += ssort[w][t];
        sT[w][lane] = make_float2(ss, (float)(npos - lane));
    }
    __syncwarp();

    float accA = 0.f, accB = 0.f, accC = 0.f;
    const float* Sw = ssort[w];
#pragma unroll
    for (int it = 0; it < 16; it++) {
        int c = (it << 5) + lane;
        float dq = row[c];
        int hi  = (Sw[15] <= dq);
        int idx = (Sw[7] <= dq) ? 8 : 0;
        idx += (Sw[idx + 3] <= dq) ? 4 : 0;
        idx += (Sw[idx + 1] <= dq) ? 2 : 0;
        idx += (Sw[idx]     <= dq) ? 1 : 0;
        idx = hi ? 16 : idx;
        if (slbl[c] != La) {
            float2 tt = sT[w][idx];
            accA += tt.x;
            accB  = fmaf(tt.y, dq, accB);
            accC += tt.y;
        }
    }

    float loss = accA - accB;
#pragma unroll
    for (int o = 16; o; o >>= 1) {
        loss += __shfl_xor_sync(0xffffffffu, loss, o);
        accC += __shfl_xor_sync(0xffffffffu, accC, o);
    }
    if (lane == 0) {
        atomicAdd(&g_psum[p], loss);
        atomicAdd(&g_pcnt[p], accC);
    }
}

__global__ void final_kernel(float* __restrict__ out, int out_size) {
    if (threadIdx.x == 0 && blockIdx.x == 0) {
        float a = 0.f, b = 0.f;
        for (int p = 0; p < NP; p++) {
            float c = g_pcnt[p];
            a += (c > 0.f) ? (g_psum[p] / fmaxf(c, 1.f)) : 0.f;
            b += c;
        }
        out[0] = a / (float)NP;
        if (out_size > 1) out[1] = b / (float)NP;
    }
}

extern "C" void kernel_launch(void* const* d_in, const int* in_sizes, int n_in,
                              void* d_out, int out_size) {
    const float* feat   = (const float*)d_in[0];
    const int*   rawlbl = (const int*)d_in[1];
    (void)in_sizes; (void)n_in;

    cudaFuncSetAttribute(mma_gemm_kernel, cudaFuncAttributeMaxDynamicSharedMemorySize, SMEM_TOTAL);

    prep_kernel<<<NP, 256>>>(rawlbl);
    norm_kernel<<<4096, 256>>>(feat);
    dim3 g(10, NP);
    mma_gemm_kernel<<<g, 256, SMEM_TOTAL>>>(feat);
    hinge_kernel<<<4096, 256>>>();
    final_kernel<<<1, 32>>>((float*)d_out, out_size);
}

// round 5
// speedup vs baseline: 2.8537x; 1.2194x over previous
#include <cuda_runtime.h>
#include <cuda_bf16.h>
#include <cstdint>
#include <math.h>

#define NP 64
#define MM 512
#define DD 256
#define MARGIN 0.2f

__device__ float  g_norm[NP * MM];
__device__ int    g_label[NP * MM];
__device__ float  g_psum[NP];
__device__ float  g_pcnt[NP];
__device__ float  g_tsort[(size_t)NP * MM * 16];   // per-anchor sorted C values
__device__ float2 g_tsuf [(size_t)NP * MM * 17];   // per-anchor (suffix sum, count)

// off-diagonal tile map (6 tiles of the 4x4 upper triangle)
__constant__ int c_oby[6] = {0,0,0,1,1,2};
__constant__ int c_obx[6] = {1,2,3,2,3,3};

// ---------------------------------------------------------------------------
__global__ void prep_kernel(const int* __restrict__ raw) {
    int is32 = (raw[33] != 0);
    int p = blockIdx.x;
    for (int c = threadIdx.x; c < MM; c += blockDim.x) {
        int idx = p * MM + c;
        g_label[idx] = is32 ? raw[idx] : raw[idx << 1];
    }
    if (p == 0 && threadIdx.x < NP) {
        g_psum[threadIdx.x] = 0.f;
        g_pcnt[threadIdx.x] = 0.f;
    }
}

__global__ __launch_bounds__(256) void norm_kernel(const float* __restrict__ feat) {
    int row  = (blockIdx.x << 3) + (threadIdx.x >> 5);
    int lane = threadIdx.x & 31;
    const float4* f = reinterpret_cast<const float4*>(feat + (size_t)row * DD);
    float s = 0.f;
#pragma unroll
    for (int u = 0; u < 2; u++) {
        float4 v = f[lane + (u << 5)];
        s += v.x * v.x + v.y * v.y + v.z * v.z + v.w * v.w;
    }
#pragma unroll
    for (int o = 16; o; o >>= 1) s += __shfl_xor_sync(0xffffffffu, s, o);
    if (lane == 0) g_norm[row] = s;
}

// ---------------------------------------------------------------------------
__device__ __forceinline__ void split2(float x0, float x1, uint32_t& hi, uint32_t& lo) {
    uint32_t h;
    asm("cvt.rn.bf16x2.f32 %0, %1, %2;" : "=r"(h) : "f"(x1), "f"(x0));
    float h0 = __uint_as_float(h << 16);
    float h1 = __uint_as_float(h & 0xFFFF0000u);
    float r0 = x0 - h0, r1 = x1 - h1;
    asm("cvt.rn.bf16x2.f32 %0, %1, %2;" : "=r"(lo) : "f"(r1), "f"(r0));
    hi = h;
}

#define MMA16816(c0,c1,c2,c3, a0,a1,a2,a3, b0,b1) \
    asm volatile("mma.sync.aligned.m16n8k16.row.col.f32.bf16.bf16.f32 " \
                 "{%0,%1,%2,%3}, {%4,%5,%6,%7}, {%8,%9}, {%0,%1,%2,%3};" \
                 : "+f"(c0), "+f"(c1), "+f"(c2), "+f"(c3) \
                 : "r"(a0), "r"(a1), "r"(a2), "r"(a3), "r"(b0), "r"(b1))

// SMEM layout. Mainloop operands live at [0, 40960); epilogue tables reuse
// that region after a barrier. Norms/labels/reduce live above, no overlap.
#define LDA 40
#define TILE_B (128 * LDA * 2)        // 10240
#define OFF_AHI 0
#define OFF_ALO (TILE_B)
#define OFF_BHI (2 * TILE_B)
#define OFF_BLO (3 * TILE_B)          // operands end at 40960
#define OFF_SR  0                     // float [128*17]  -> 8704
#define OFF_TR  8704                  // float2[128*17]  -> 26112
#define OFF_SC  26112                 // float [128*17] (B1: sPos 128*16) -> 34816
#define OFF_TC  34816                 // float2[128*17]  -> 52224
#define OFF_NRM 52224                 // 256 floats      -> 53248
#define OFF_LBL 53248                 // 256 ints        -> 54272
#define OFF_RED 54272                 // 16 floats       -> 54336
#define SMEM_TOTAL 54528

__device__ __forceinline__ void load_chunk(
    const float* __restrict__ src, int k0, char* smem, int off_hi, int off_lo, int tid)
{
    uint16_t* shi = reinterpret_cast<uint16_t*>(smem + off_hi);
    uint16_t* slo = reinterpret_cast<uint16_t*>(smem + off_lo);
#pragma unroll
    for (int it = 0; it < 4; it++) {
        int q   = tid + (it << 8);
        int row = q >> 3;
        int c4  = q & 7;
        float4 v = *reinterpret_cast<const float4*>(src + (size_t)row * DD + k0 + (c4 << 2));
        uint32_t h0, h1, l0, l1;
        split2(v.x, v.y, h0, l0);
        split2(v.z, v.w, h1, l1);
        int idx = row * LDA + (c4 << 2);
        *reinterpret_cast<uint2*>(&shi[idx]) = make_uint2(h0, h1);
        *reinterpret_cast<uint2*>(&slo[idx]) = make_uint2(l0, l1);
    }
}

__device__ __forceinline__ void search_acc(
    const float* __restrict__ S, const float2* __restrict__ T, float d,
    float& aA, float& aB, float& aC)
{
    int hi  = (S[15] <= d);
    int idx = (S[7] <= d) ? 8 : 0;
    idx += (S[idx + 3] <= d) ? 4 : 0;
    idx += (S[idx + 1] <= d) ? 2 : 0;
    idx += (S[idx]     <= d) ? 1 : 0;
    idx = hi ? 16 : idx;
    float2 t = T[idx];
    aA += t.x;
    aB  = fmaf(t.y, d, aB);
    aC += t.y;
}

// ---------------------------------------------------------------------------
// fused GEMM + hinge. DIAG: builds per-anchor tables from its own diagonal
// class blocks, processes row-direction contributions, publishes tables.
// !DIAG: loads tables for both blocks, processes both directions per element.
// ---------------------------------------------------------------------------
template<bool DIAG>
__global__ void __launch_bounds__(256) fused_kernel(const float* __restrict__ feat) {
    extern __shared__ char smem[];
    const int tid = threadIdx.x;
    const int w = tid >> 5, lane = tid & 31;
    const int g = lane >> 2, tg = lane & 3;
    const int wm = w >> 1, wn = w & 1;
    const int p = blockIdx.y;
    const int by = DIAG ? blockIdx.x : c_oby[blockIdx.x];
    const int bx = DIAG ? blockIdx.x : c_obx[blockIdx.x];

    float* sNi = reinterpret_cast<float*>(smem + OFF_NRM);
    float* sNj = sNi + 128;
    int*   sLR = reinterpret_cast<int*>(smem + OFF_LBL);
    int*   sLC = sLR + 128;
    if (tid < 128) {
        sNi[tid] = g_norm[p * MM + by * 128 + tid];
        sLR[tid] = g_label[p * MM + by * 128 + tid];
        if (DIAG) { sNj[tid] = sNi[tid]; }
        else {
            sNj[tid] = g_norm[p * MM + bx * 128 + tid];
            sLC[tid] = g_label[p * MM + bx * 128 + tid];
        }
    }

    const float* Abase = feat + ((size_t)p * MM + (size_t)by * 128) * DD;
    const float* Bbase = feat + ((size_t)p * MM + (size_t)bx * 128) * DD;

    const uint16_t* sAhi = reinterpret_cast<const uint16_t*>(smem + OFF_AHI);
    const uint16_t* sAlo = reinterpret_cast<const uint16_t*>(smem + OFF_ALO);
    const uint16_t* sBhi = reinterpret_cast<const uint16_t*>(smem + (DIAG ? OFF_AHI : OFF_BHI));
    const uint16_t* sBlo = reinterpret_cast<const uint16_t*>(smem + (DIAG ? OFF_ALO : OFF_BLO));

    float c[2][8][4];
#pragma unroll
    for (int mi = 0; mi < 2; mi++)
#pragma unroll
        for (int ni = 0; ni < 8; ni++)
#pragma unroll
            for (int r = 0; r < 4; r++) c[mi][ni][r] = 0.f;

#pragma unroll 1
    for (int ch = 0; ch < 8; ch++) {
        int k0 = ch << 5;
        __syncthreads();
        load_chunk(Abase, k0, smem, OFF_AHI, OFF_ALO, tid);
        if (!DIAG) load_chunk(Bbase, k0, smem, OFF_BHI, OFF_BLO, tid);
        __syncthreads();

#pragma unroll
        for (int ks = 0; ks < 2; ks++) {
            int kk = (ks << 4) + (tg << 1);
            uint32_t ah[2][4], al[2][4];
#pragma unroll
            for (int mi = 0; mi < 2; mi++) {
                int r0 = ((wm << 5) + (mi << 4) + g) * LDA + kk;
                int r1 = r0 + (LDA << 3);
                ah[mi][0] = *reinterpret_cast<const uint32_t*>(&sAhi[r0]);
                ah[mi][1] = *reinterpret_cast<const uint32_t*>(&sAhi[r1]);
                ah[mi][2] = *reinterpret_cast<const uint32_t*>(&sAhi[r0 + 8]);
                ah[mi][3] = *reinterpret_cast<const uint32_t*>(&sAhi[r1 + 8]);
                al[mi][0] = *reinterpret_cast<const uint32_t*>(&sAlo[r0]);
                al[mi][1] = *reinterpret_cast<const uint32_t*>(&sAlo[r1]);
                al[mi][2] = *reinterpret_cast<const uint32_t*>(&sAlo[r0 + 8]);
                al[mi][3] = *reinterpret_cast<const uint32_t*>(&sAlo[r1 + 8]);
            }
            uint32_t bh[8][2], bl[8][2];
#pragma unroll
            for (int ni = 0; ni < 8; ni++) {
                int rb = ((wn << 6) + (ni << 3) + g) * LDA + kk;
                bh[ni][0] = *reinterpret_cast<const uint32_t*>(&sBhi[rb]);
                bh[ni][1] = *reinterpret_cast<const uint32_t*>(&sBhi[rb + 8]);
                bl[ni][0] = *reinterpret_cast<const uint32_t*>(&sBlo[rb]);
                bl[ni][1] = *reinterpret_cast<const uint32_t*>(&sBlo[rb + 8]);
            }
#pragma unroll
            for (int mi = 0; mi < 2; mi++)
#pragma unroll
                for (int ni = 0; ni < 8; ni++) {
                    MMA16816(c[mi][ni][0], c[mi][ni][1], c[mi][ni][2], c[mi][ni][3],
                             ah[mi][0], ah[mi][1], ah[mi][2], ah[mi][3],
                             bh[ni][0], bh[ni][1]);
                    MMA16816(c[mi][ni][0], c[mi][ni][1], c[mi][ni][2], c[mi][ni][3],
                             ah[mi][0], ah[mi][1], ah[mi][2], ah[mi][3],
                             bl[ni][0], bl[ni][1]);
                    MMA16816(c[mi][ni][0], c[mi][ni][1], c[mi][ni][2], c[mi][ni][3],
                             al[mi][0], al[mi][1], al[mi][2], al[mi][3],
                             bh[ni][0], bh[ni][1]);
                }
        }
    }
    __syncthreads();   // all operand reads done before table region is reused

    // distances in place of accumulators
#pragma unroll
    for (int mi = 0; mi < 2; mi++) {
        int i0 = (wm << 5) + (mi << 4) + g;
#pragma unroll
        for (int ni = 0; ni < 8; ni++) {
            int j0 = (wn << 6) + (ni << 3) + (tg << 1);
            c[mi][ni][0] = sqrtf(fmaxf(sNi[i0]     + sNj[j0]     - 2.f * c[mi][ni][0], 0.f));
            c[mi][ni][1] = sqrtf(fmaxf(sNi[i0]     + sNj[j0 + 1] - 2.f * c[mi][ni][1], 0.f));
            c[mi][ni][2] = sqrtf(fmaxf(sNi[i0 + 8] + sNj[j0]     - 2.f * c[mi][ni][2], 0.f));
            c[mi][ni][3] = sqrtf(fmaxf(sNi[i0 + 8] + sNj[j0 + 1] - 2.f * c[mi][ni][3], 0.f));
        }
    }

    float* sSR = reinterpret_cast<float*>(smem + OFF_SR);
    float2* sTR = reinterpret_cast<float2*>(smem + OFF_TR);
    float* sSC = reinterpret_cast<float*>(smem + OFF_SC);
    float2* sTC = reinterpret_cast<float2*>(smem + OFF_TC);

    if (DIAG) {
        // scatter same-label C values (class blocks are 16-aligned)
        float* sPos = reinterpret_cast<float*>(smem + OFF_SC);
#pragma unroll
        for (int mi = 0; mi < 2; mi++) {
            int ia = (wm << 5) + (mi << 4) + g, ib = ia + 8;
#pragma unroll
            for (int ni = 0; ni < 8; ni++) {
                int j0 = (wn << 6) + (ni << 3) + (tg << 1);
                if (sLR[ia] == sLR[j0])     sPos[ia * 16 + (j0 & 15)]       = MARGIN + c[mi][ni][0];
                if (sLR[ia] == sLR[j0 + 1]) sPos[ia * 16 + ((j0 + 1) & 15)] = MARGIN + c[mi][ni][1];
                if (sLR[ib] == sLR[j0])     sPos[ib * 16 + (j0 & 15)]       = MARGIN + c[mi][ni][2];
                if (sLR[ib] == sLR[j0 + 1]) sPos[ib * 16 + ((j0 + 1) & 15)] = MARGIN + c[mi][ni][3];
            }
        }
        __syncthreads();
        // per-anchor tables: branchless rank sort + suffix sums; publish
        if (tid < 128) {
            float v[16];
#pragma unroll
            for (int k = 0; k < 16; k++) v[k] = sPos[tid * 16 + k];
#pragma unroll
            for (int k = 0; k < 16; k++) {
                int r = 0;
#pragma unroll
                for (int j = 0; j < 16; j++)
                    r += (int)((v[j] < v[k]) | ((v[j] == v[k]) & (j < k)));
                sSR[tid * 17 + r] = v[k];
            }
            float ss = 0.f;
            sTR[tid * 17 + 16] = make_float2(0.f, 0.f);
#pragma unroll
            for (int k = 15; k >= 0; k--) {
                ss += sSR[tid * 17 + k];
                sTR[tid * 17 + k] = make_float2(ss, (float)(16 - k));
            }
            size_t ab = (size_t)p * MM + by * 128 + tid;
#pragma unroll
            for (int k = 0; k < 16; k++) g_tsort[ab * 16 + k] = sSR[tid * 17 + k];
#pragma unroll
            for (int k = 0; k < 17; k++) g_tsuf[ab * 17 + k] = sTR[tid * 17 + k];
        }
        __syncthreads();
    } else {
        // load row + col tables (operand smem is dead)
        size_t rb = (size_t)p * MM + by * 128;
        size_t cb = (size_t)p * MM + bx * 128;
        for (int q = tid; q < 128 * 16; q += 256) {
            int a = q >> 4, k = q & 15;
            sSR[a * 17 + k] = g_tsort[(rb + a) * 16 + k];
            sSC[a * 17 + k] = g_tsort[(cb + a) * 16 + k];
        }
        for (int q = tid; q < 128 * 17; q += 256) {
            int a = q / 17, k = q % 17;
            sTR[a * 17 + k] = g_tsuf[(rb + a) * 17 + k];
            sTC[a * 17 + k] = g_tsuf[(cb + a) * 17 + k];
        }
        __syncthreads();
    }

    // hinge contributions
    float aA = 0.f, aB = 0.f, aC = 0.f;
#pragma unroll
    for (int mi = 0; mi < 2; mi++) {
        int ia = (wm << 5) + (mi << 4) + g, ib = ia + 8;
        int lA = sLR[ia], lB = sLR[ib];
        const float*  SA = &sSR[ia * 17]; const float2* TA = &sTR[ia * 17];
        const float*  SB = &sSR[ib * 17]; const float2* TB = &sTR[ib * 17];
#pragma unroll
        for (int ni = 0; ni < 8; ni++) {
            int j0 = (wn << 6) + (ni << 3) + (tg << 1);
#pragma unroll
            for (int e = 0; e < 2; e++) {
                int j = j0 + e;
                int lj = DIAG ? sLR[j] : sLC[j];
                float d0 = c[mi][ni][e], d1 = c[mi][ni][2 + e];
                if (lA != lj) {
                    search_acc(SA, TA, d0, aA, aB, aC);
                    if (!DIAG) search_acc(&sSC[j * 17], &sTC[j * 17], d0, aA, aB, aC);
                }
                if (lB != lj) {
                    search_acc(SB, TB, d1, aA, aB, aC);
                    if (!DIAG) search_acc(&sSC[j * 17], &sTC[j * 17], d1, aA, aB, aC);
                }
            }
        }
    }

    float loss = aA - aB, cnt = aC;
#pragma unroll
    for (int o = 16; o; o >>= 1) {
        loss += __shfl_xor_sync(0xffffffffu, loss, o);
        cnt  += __shfl_xor_sync(0xffffffffu, cnt, o);
    }
    float* sRed = reinterpret_cast<float*>(smem + OFF_RED);
    if (lane == 0) { sRed[w] = loss; sRed[8 + w] = cnt; }
    __syncthreads();
    if (tid == 0) {
        float L = 0.f, C = 0.f;
#pragma unroll
        for (int k = 0; k < 8; k++) { L += sRed[k]; C += sRed[8 + k]; }
        atomicAdd(&g_psum[p], L);
        atomicAdd(&g_pcnt[p], C);
    }
}

__global__ void final_kernel(float* __restrict__ out, int out_size) {
    if (threadIdx.x == 0 && blockIdx.x == 0) {
        float a = 0.f, b = 0.f;
        for (int p = 0; p < NP; p++) {
            float c = g_pcnt[p];
            a += (c > 0.f) ? (g_psum[p] / fmaxf(c, 1.f)) : 0.f;
            b += c;
        }
        out[0] = a / (float)NP;
        if (out_size > 1) out[1] = b / (float)NP;
    }
}

extern "C" void kernel_launch(void* const* d_in, const int* in_sizes, int n_in,
                              void* d_out, int out_size) {
    const float* feat   = (const float*)d_in[0];
    const int*   rawlbl = (const int*)d_in[1];
    (void)in_sizes; (void)n_in;

    cudaFuncSetAttribute(fused_kernel<true>,  cudaFuncAttributeMaxDynamicSharedMemorySize, SMEM_TOTAL);
    cudaFuncSetAttribute(fused_kernel<false>, cudaFuncAttributeMaxDynamicSharedMemorySize, SMEM_TOTAL);

    prep_kernel<<<NP, 256>>>(rawlbl);
    norm_kernel<<<4096, 256>>>(feat);
    dim3 gd(4, NP), go(6, NP);
    fused_kernel<true><<<gd, 256, SMEM_TOTAL>>>(feat);
    fused_kernel<false><<<go, 256, SMEM_TOTAL>>>(feat);
    final_kernel<<<1, 32>>>((float*)d_out, out_size);
}